// round 1
// baseline (speedup 1.0000x reference)
#include <cuda_runtime.h>
#include <math.h>

#define S_LEN   2048
#define BATCH   4
#define HEADS   16
#define HD      64
#define DMODEL  1024
#define LDT     68   // padded smem row length for attention tiles

// -------- device-global scratch (allocation-guard-safe) --------
__device__ float g_q[BATCH*HEADS*S_LEN*HD];    // [B,H,S,hd] RoPE'd
__device__ float g_k[BATCH*HEADS*S_LEN*HD];    // [B,H,S,hd] RoPE'd
__device__ float g_v[BATCH*HEADS*S_LEN*HD];    // [B,H,S,hd]
__device__ float g_att[BATCH*S_LEN*DMODEL];    // [B,S,D] attention output
__device__ float g_cos[S_LEN*(HD/2)];
__device__ float g_sin[S_LEN*(HD/2)];

// -------- RoPE table init --------
__global__ void rope_init_kernel() {
    int idx = blockIdx.x * blockDim.x + threadIdx.x;
    if (idx >= S_LEN * (HD/2)) return;
    int s = idx >> 5;           // position
    int i = idx & 31;           // pair index
    double freq = pow(10000.0, -2.0 * (double)i / (double)HD);
    double ang  = (double)s * freq;
    g_cos[idx] = (float)cos(ang);
    g_sin[idx] = (float)sin(ang);
}

// -------- 128x128x8 register-tiled SGEMM: C = A @ W^T --------
// MODE 0: A = x [8192,1024], W = w_qkv [3072,1024]; epilogue applies RoPE and
//         scatters to g_q/g_k/g_v in [B,H,S,hd] layout.
// MODE 1: A = g_att [8192,1024], W = w_o [1024,1024]; epilogue writes C row-major.
template<int MODE>
__global__ __launch_bounds__(256) void gemm_kernel(const float* __restrict__ Ain,
                                                   const float* __restrict__ W,
                                                   float* __restrict__ C, int N) {
    const float* A = (MODE == 1) ? (const float*)g_att : Ain;
    const int K = 1024;
    __shared__ float As[8][128];
    __shared__ float Bs[8][128];

    int tid = threadIdx.x;
    int tx = tid & 15;          // col group
    int ty = tid >> 4;          // row group
    int m0 = blockIdx.y * 128;
    int n0 = blockIdx.x * 128;
    int lr = tid >> 1;          // 0..127 row within tile for loads
    int lk = (tid & 1) * 4;     // 0 or 4

    float acc[8][8];
#pragma unroll
    for (int i = 0; i < 8; i++)
#pragma unroll
        for (int j = 0; j < 8; j++) acc[i][j] = 0.f;

    const float* Aptr = A + (m0 + lr) * K + lk;
    const float* Wptr = W + (n0 + lr) * K + lk;

    for (int k0 = 0; k0 < K; k0 += 8) {
        float4 av = *(const float4*)(Aptr + k0);
        float4 bv = *(const float4*)(Wptr + k0);
        __syncthreads();
        As[lk+0][lr] = av.x; As[lk+1][lr] = av.y; As[lk+2][lr] = av.z; As[lk+3][lr] = av.w;
        Bs[lk+0][lr] = bv.x; Bs[lk+1][lr] = bv.y; Bs[lk+2][lr] = bv.z; Bs[lk+3][lr] = bv.w;
        __syncthreads();
#pragma unroll
        for (int kk = 0; kk < 8; kk++) {
            float4 a0 = *(const float4*)&As[kk][ty*8];
            float4 a1 = *(const float4*)&As[kk][ty*8 + 4];
            float4 b0 = *(const float4*)&Bs[kk][tx*8];
            float4 b1 = *(const float4*)&Bs[kk][tx*8 + 4];
            float ar[8] = {a0.x,a0.y,a0.z,a0.w,a1.x,a1.y,a1.z,a1.w};
            float br[8] = {b0.x,b0.y,b0.z,b0.w,b1.x,b1.y,b1.z,b1.w};
#pragma unroll
            for (int i = 0; i < 8; i++)
#pragma unroll
                for (int j = 0; j < 8; j++)
                    acc[i][j] += ar[i] * br[j];
        }
    }

    if (MODE == 0) {
#pragma unroll
        for (int i = 0; i < 8; i++) {
            int mg = m0 + ty*8 + i;
            int bb = mg >> 11;           // batch
            int ss = mg & 2047;          // seq pos
#pragma unroll
            for (int j = 0; j < 8; j += 2) {
                int ng   = n0 + tx*8 + j;
                int sect = ng >> 10;     // 0=q, 1=k, 2=v
                int col  = ng & 1023;
                int h    = col >> 6;
                int d    = col & 63;
                int di = ((bb*HEADS + h)*S_LEN + ss)*HD + d;
                float v0 = acc[i][j], v1 = acc[i][j+1];
                if (sect == 2) {
                    g_v[di] = v0; g_v[di+1] = v1;
                } else {
                    float c  = g_cos[ss*32 + (d>>1)];
                    float sn = g_sin[ss*32 + (d>>1)];
                    float r0 = v0*c - v1*sn;
                    float r1 = v0*sn + v1*c;
                    if (sect == 0) { g_q[di] = r0; g_q[di+1] = r1; }
                    else           { g_k[di] = r0; g_k[di+1] = r1; }
                }
            }
        }
    } else {
#pragma unroll
        for (int i = 0; i < 8; i++) {
            int mg = m0 + ty*8 + i;
#pragma unroll
            for (int j = 0; j < 8; j++)
                C[mg * N + n0 + tx*8 + j] = acc[i][j];
        }
    }
}

// -------- flash attention: BQ=64, BK=64, 128 threads, 8x4 microtile --------
// Thread (tx 0..15, ty 0..7): scores rows ty*8..+7, key cols tx*4..+3,
// PV output rows ty*8..+7, head-dim cols tx*4..+3.
__global__ __launch_bounds__(128) void attn_kernel(const int* __restrict__ pm) {
    extern __shared__ float sm[];
    float* Qt = sm;                 // [64 d][LDT rows]  Q transposed
    float* KP = sm + 64*LDT;        // K transposed [d][key], reused as Pt [key][qrow]
    float* Vs = sm + 2*64*LDT;      // [key][d]

    int qt = (int)gridDim.x - 1 - (int)blockIdx.x;   // big tiles first (load balance)
    int bh = blockIdx.y;
    int b  = bh >> 4;
    int h  = bh & 15;
    int tid = threadIdx.x;
    int tx = tid & 15;
    int ty = tid >> 4;

    const float* qbase = g_q + bh * (S_LEN*HD);
    const float* kbase = g_k + bh * (S_LEN*HD);
    const float* vbase = g_v + bh * (S_LEN*HD);
    const int*   pmb   = pm + b * S_LEN;

    // load Q tile transposed: Qt[d][r]
    for (int idx = tid; idx < 64*64; idx += 128) {
        int d = idx & 63, r = idx >> 6;
        Qt[d*LDT + r] = qbase[(qt*64 + r)*HD + d];
    }

    float m_i[8], l_i[8], o[8][4];
#pragma unroll
    for (int i = 0; i < 8; i++) {
        m_i[i] = -1e30f; l_i[i] = 0.f;
#pragma unroll
        for (int j = 0; j < 4; j++) o[i][j] = 0.f;
    }

    for (int kt = 0; kt <= qt; kt++) {
        __syncthreads();   // previous iteration's readers done (also covers Qt on iter 0)
        for (int idx = tid; idx < 64*64; idx += 128) {
            int d = idx & 63, r = idx >> 6;
            int g = (kt*64 + r)*HD + d;
            KP[d*LDT + r] = kbase[g];   // K transposed
            Vs[r*LDT + d] = vbase[g];
        }
        __syncthreads();

        // scores: sc[i][j] = sum_k Q[qr+i][k] * K[kc+j][k]
        float sc[8][4];
#pragma unroll
        for (int i = 0; i < 8; i++)
#pragma unroll
            for (int j = 0; j < 4; j++) sc[i][j] = 0.f;

#pragma unroll 8
        for (int k = 0; k < 64; k++) {
            float4 q0 = *(const float4*)&Qt[k*LDT + ty*8];
            float4 q1 = *(const float4*)&Qt[k*LDT + ty*8 + 4];
            float4 kv = *(const float4*)&KP[k*LDT + tx*4];
            float qa[8] = {q0.x,q0.y,q0.z,q0.w,q1.x,q1.y,q1.z,q1.w};
            float kb[4] = {kv.x,kv.y,kv.z,kv.w};
#pragma unroll
            for (int i = 0; i < 8; i++)
#pragma unroll
                for (int j = 0; j < 4; j++)
                    sc[i][j] += qa[i] * kb[j];
        }

        // scale + causal + padding mask
        int kg[4], pmask[4];
#pragma unroll
        for (int j = 0; j < 4; j++) {
            kg[j] = kt*64 + tx*4 + j;
            pmask[j] = pmb[kg[j]];
        }
#pragma unroll
        for (int i = 0; i < 8; i++) {
            int qg = qt*64 + ty*8 + i;
#pragma unroll
            for (int j = 0; j < 4; j++) {
                float v = sc[i][j] * 0.125f;
                if (kg[j] > qg || pmask[j] == 0) v = -1e30f;
                sc[i][j] = v;
            }
        }

        // online softmax (row reductions across tx = 16-lane shuffle groups)
#pragma unroll
        for (int i = 0; i < 8; i++) {
            float tmax = fmaxf(fmaxf(sc[i][0], sc[i][1]), fmaxf(sc[i][2], sc[i][3]));
#pragma unroll
            for (int off = 8; off >= 1; off >>= 1)
                tmax = fmaxf(tmax, __shfl_xor_sync(0xffffffffu, tmax, off));
            float mn = fmaxf(m_i[i], tmax);
            float psum = 0.f;
#pragma unroll
            for (int j = 0; j < 4; j++) {
                float p = (sc[i][j] > -1e29f) ? __expf(sc[i][j] - mn) : 0.f;
                sc[i][j] = p;
                psum += p;
            }
#pragma unroll
            for (int off = 8; off >= 1; off >>= 1)
                psum += __shfl_xor_sync(0xffffffffu, psum, off);
            float alpha = (m_i[i] > -1e29f) ? __expf(m_i[i] - mn) : 0.f;
            l_i[i] = l_i[i] * alpha + psum;
            m_i[i] = mn;
#pragma unroll
            for (int j = 0; j < 4; j++) o[i][j] *= alpha;
        }

        __syncthreads();   // everyone done reading K before overwriting with P
        // write Pt[key][qrow] into KP
#pragma unroll
        for (int j = 0; j < 4; j++) {
            float4 p0 = make_float4(sc[0][j], sc[1][j], sc[2][j], sc[3][j]);
            float4 p1 = make_float4(sc[4][j], sc[5][j], sc[6][j], sc[7][j]);
            *(float4*)&KP[(tx*4 + j)*LDT + ty*8]     = p0;
            *(float4*)&KP[(tx*4 + j)*LDT + ty*8 + 4] = p1;
        }
        __syncthreads();

        // PV: o[i][j] += sum_k P[qr+i][k] * V[k][dc+j]
#pragma unroll 8
        for (int k = 0; k < 64; k++) {
            float4 p0 = *(const float4*)&KP[k*LDT + ty*8];
            float4 p1 = *(const float4*)&KP[k*LDT + ty*8 + 4];
            float4 vv = *(const float4*)&Vs[k*LDT + tx*4];
            float pa[8] = {p0.x,p0.y,p0.z,p0.w,p1.x,p1.y,p1.z,p1.w};
            float vb[4] = {vv.x,vv.y,vv.z,vv.w};
#pragma unroll
            for (int i = 0; i < 8; i++)
#pragma unroll
                for (int j = 0; j < 4; j++)
                    o[i][j] += pa[i] * vb[j];
        }
    }

    // finalize and store to [B,S,H,hd] (= [B,S,D] contiguous)
#pragma unroll
    for (int i = 0; i < 8; i++) {
        float inv = 1.f / l_i[i];
        int srow = qt*64 + ty*8 + i;
        float* dst = g_att + ((b*S_LEN + srow)*HEADS + h)*HD + tx*4;
#pragma unroll
        for (int j = 0; j < 4; j++) dst[j] = o[i][j] * inv;
    }
}

extern "C" void kernel_launch(void* const* d_in, const int* in_sizes, int n_in,
                              void* d_out, int out_size) {
    const float* x     = (const float*)d_in[0];
    const int*   pmask = (const int*)  d_in[1];
    const float* w_qkv = (const float*)d_in[2];
    const float* w_o   = (const float*)d_in[3];
    float* out = (float*)d_out;

    const int attn_smem = 3 * 64 * LDT * 4;   // 52224 B
    cudaFuncSetAttribute(attn_kernel, cudaFuncAttributeMaxDynamicSharedMemorySize, attn_smem);

    rope_init_kernel<<<64, 1024>>>();
    gemm_kernel<0><<<dim3(24, 64), 256>>>(x, w_qkv, nullptr, 3072);
    attn_kernel<<<dim3(32, 64), 128, attn_smem>>>(pmask);
    gemm_kernel<1><<<dim3(8, 64), 256>>>(nullptr, w_o, out, 1024);
}

// round 4
// speedup vs baseline: 1.5162x; 1.5162x over previous
#include <cuda_runtime.h>
#include <cuda_bf16.h>
#include <math.h>
#include <stdint.h>

#define S_LEN   2048
#define BATCH   4
#define HEADS   16
#define HD      64
#define DMODEL  1024
#define LDT     68
#define SROW    40   // smem row stride in bf16 (80B -> conflict-free ldmatrix)

// -------- device-global scratch --------
__device__ float g_q[BATCH*HEADS*S_LEN*HD];
__device__ float g_k[BATCH*HEADS*S_LEN*HD];
__device__ float g_v[BATCH*HEADS*S_LEN*HD];
__device__ float g_att[BATCH*S_LEN*DMODEL];
__device__ float g_cos[S_LEN*(HD/2)];
__device__ float g_sin[S_LEN*(HD/2)];
__device__ __nv_bfloat16 g_xhi[BATCH*S_LEN*DMODEL];
__device__ __nv_bfloat16 g_xlo[BATCH*S_LEN*DMODEL];
__device__ __nv_bfloat16 g_whi[3*DMODEL*DMODEL];
__device__ __nv_bfloat16 g_wlo[3*DMODEL*DMODEL];
__device__ __nv_bfloat16 g_wohi[DMODEL*DMODEL];
__device__ __nv_bfloat16 g_wolo[DMODEL*DMODEL];
__device__ __nv_bfloat16 g_atthi[BATCH*S_LEN*DMODEL];
__device__ __nv_bfloat16 g_attlo[BATCH*S_LEN*DMODEL];

// ================= PTX helpers (base sm_10x only — no 'a' features) ========
__device__ __forceinline__ uint32_t smem_u32(const void* p) {
    uint32_t a;
    asm("{ .reg .u64 t; cvta.to.shared.u64 t, %1; cvt.u32.u64 %0, t; }" : "=r"(a) : "l"(p));
    return a;
}
__device__ __forceinline__ void ldsm_x4(uint32_t* r, uint32_t addr) {
    asm volatile("ldmatrix.sync.aligned.m8n8.x4.shared.b16 {%0,%1,%2,%3}, [%4];"
        : "=r"(r[0]), "=r"(r[1]), "=r"(r[2]), "=r"(r[3]) : "r"(addr));
}
__device__ __forceinline__ void mma16816(float* d, const uint32_t* a, const uint32_t* b) {
    asm volatile("mma.sync.aligned.m16n8k16.row.col.f32.bf16.bf16.f32 "
        "{%0,%1,%2,%3}, {%4,%5,%6,%7}, {%8,%9}, {%0,%1,%2,%3};"
        : "+f"(d[0]), "+f"(d[1]), "+f"(d[2]), "+f"(d[3])
        : "r"(a[0]), "r"(a[1]), "r"(a[2]), "r"(a[3]), "r"(b[0]), "r"(b[1]));
}

// ================= RoPE table =================
__global__ void rope_init_kernel() {
    int idx = blockIdx.x * blockDim.x + threadIdx.x;
    if (idx >= S_LEN * (HD/2)) return;
    int s = idx >> 5;
    int i = idx & 31;
    double freq = pow(10000.0, -2.0 * (double)i / (double)HD);
    double ang  = (double)s * freq;
    g_cos[idx] = (float)cos(ang);
    g_sin[idx] = (float)sin(ang);
}

// ================= fp32 -> bf16 hi/lo split =================
template<int WHICH>
__global__ __launch_bounds__(256) void conv_kernel(const float* __restrict__ srcp) {
    constexpr int n = (WHICH == 0) ? BATCH*S_LEN*DMODEL :
                      (WHICH == 1) ? 3*DMODEL*DMODEL :
                      (WHICH == 2) ? DMODEL*DMODEL : BATCH*S_LEN*DMODEL;
    const float* src = (WHICH == 3) ? (const float*)g_att : srcp;
    __nv_bfloat16* hi = (WHICH == 0) ? g_xhi : (WHICH == 1) ? g_whi :
                        (WHICH == 2) ? g_wohi : g_atthi;
    __nv_bfloat16* lo = (WHICH == 0) ? g_xlo : (WHICH == 1) ? g_wlo :
                        (WHICH == 2) ? g_wolo : g_attlo;
    int i = (blockIdx.x * blockDim.x + threadIdx.x) * 4;
    if (i >= n) return;
    float4 v = *(const float4*)(src + i);
    float vv[4] = {v.x, v.y, v.z, v.w};
    uint32_t hp[2], lp[2];
#pragma unroll
    for (int j = 0; j < 2; j++) {
        __nv_bfloat16 h0 = __float2bfloat16(vv[2*j]);
        __nv_bfloat16 h1 = __float2bfloat16(vv[2*j+1]);
        __nv_bfloat16 l0 = __float2bfloat16(vv[2*j]   - __bfloat162float(h0));
        __nv_bfloat16 l1 = __float2bfloat16(vv[2*j+1] - __bfloat162float(h1));
        hp[j] = (uint32_t)__bfloat16_as_ushort(h0) | ((uint32_t)__bfloat16_as_ushort(h1) << 16);
        lp[j] = (uint32_t)__bfloat16_as_ushort(l0) | ((uint32_t)__bfloat16_as_ushort(l1) << 16);
    }
    *(uint2*)(hi + i) = make_uint2(hp[0], hp[1]);
    *(uint2*)(lo + i) = make_uint2(lp[0], lp[1]);
}

// ================= mma.sync split-bf16 GEMM =================
// C[8192, N] = A @ W^T, K=1024. 128x128 block tile, 8 warps of 64x32,
// BK=32, 3-term bf16 split: Ahi*Whi + Ahi*Wlo + Alo*Whi.
// W stored [N][K] (K contiguous) == col-major B -> NON-trans ldmatrix for B.
#define GEMM_SMEM (4 * 128 * SROW * 2)   // 40960 B
template<int MODE>
__global__ __launch_bounds__(256, 2) void mma_gemm(float* __restrict__ C) {
    extern __shared__ __nv_bfloat16 smb[];
    __nv_bfloat16* sAh = smb;
    __nv_bfloat16* sAl = smb + 128*SROW;
    __nv_bfloat16* sBh = smb + 2*128*SROW;
    __nv_bfloat16* sBl = smb + 3*128*SROW;

    const __nv_bfloat16* Ahi = (MODE == 0) ? g_xhi : g_atthi;
    const __nv_bfloat16* Alo = (MODE == 0) ? g_xlo : g_attlo;
    const __nv_bfloat16* Whi = (MODE == 0) ? g_whi : g_wohi;
    const __nv_bfloat16* Wlo = (MODE == 0) ? g_wlo : g_wolo;

    const int tid = threadIdx.x, lane = tid & 31, wid = tid >> 5;
    const int warpM = wid & 1, warpN = wid >> 1;
    const int m0 = blockIdx.y * 128, n0 = blockIdx.x * 128;

    const int lrow = tid >> 2;        // 0..63
    const int lkg  = (tid & 3) * 8;   // bf16 col offset
    const size_t gA0 = (size_t)(m0 + lrow) * 1024 + lkg;
    const size_t gA1 = (size_t)(m0 + 64 + lrow) * 1024 + lkg;
    const size_t gB0 = (size_t)(n0 + lrow) * 1024 + lkg;
    const size_t gB1 = (size_t)(n0 + 64 + lrow) * 1024 + lkg;
    const int s0 = lrow * SROW + lkg;
    const int s1 = (64 + lrow) * SROW + lkg;

    const uint32_t sAh_u = smem_u32(sAh), sAl_u = smem_u32(sAl);
    const uint32_t sBh_u = smem_u32(sBh), sBl_u = smem_u32(sBl);
    const uint32_t lr = lane & 15, lc = (lane >> 4) * 8;
    const uint32_t aoff = ((warpM*64 + lr) * SROW + lc) * 2;
    const uint32_t boff = ((warpN*32 + lr) * SROW + lc) * 2;

    float acc[4][4][4];
#pragma unroll
    for (int i = 0; i < 4; i++)
#pragma unroll
        for (int j = 0; j < 4; j++)
#pragma unroll
            for (int t = 0; t < 4; t++) acc[i][j][t] = 0.f;

    for (int k0 = 0; k0 < 1024; k0 += 32) {
        __syncthreads();
        *(uint4*)(sAh + s0) = *(const uint4*)(Ahi + gA0 + k0);
        *(uint4*)(sAh + s1) = *(const uint4*)(Ahi + gA1 + k0);
        *(uint4*)(sAl + s0) = *(const uint4*)(Alo + gA0 + k0);
        *(uint4*)(sAl + s1) = *(const uint4*)(Alo + gA1 + k0);
        *(uint4*)(sBh + s0) = *(const uint4*)(Whi + gB0 + k0);
        *(uint4*)(sBh + s1) = *(const uint4*)(Whi + gB1 + k0);
        *(uint4*)(sBl + s0) = *(const uint4*)(Wlo + gB0 + k0);
        *(uint4*)(sBl + s1) = *(const uint4*)(Wlo + gB1 + k0);
        __syncthreads();

#pragma unroll
        for (int k16 = 0; k16 < 2; k16++) {
            const uint32_t kb = k16 * 32;   // byte offset for 16 bf16
            uint32_t a[4][4], b[4][2], t4[4];
            // A hi frags
#pragma unroll
            for (int mt = 0; mt < 4; mt++)
                ldsm_x4(a[mt], sAh_u + aoff + mt * (16*SROW*2) + kb);
            // B hi frags (NON-trans: W[N][K] is col-major B)
#pragma unroll
            for (int ng = 0; ng < 2; ng++) {
                ldsm_x4(t4, sBh_u + boff + ng * (16*SROW*2) + kb);
                b[2*ng][0]   = t4[0]; b[2*ng][1]   = t4[2];
                b[2*ng+1][0] = t4[1]; b[2*ng+1][1] = t4[3];
            }
#pragma unroll
            for (int mt = 0; mt < 4; mt++)
#pragma unroll
                for (int nt = 0; nt < 4; nt++)
                    mma16816(acc[mt][nt], a[mt], b[nt]);
            // B lo frags: Ahi * Wlo
#pragma unroll
            for (int ng = 0; ng < 2; ng++) {
                ldsm_x4(t4, sBl_u + boff + ng * (16*SROW*2) + kb);
                b[2*ng][0]   = t4[0]; b[2*ng][1]   = t4[2];
                b[2*ng+1][0] = t4[1]; b[2*ng+1][1] = t4[3];
            }
#pragma unroll
            for (int mt = 0; mt < 4; mt++)
#pragma unroll
                for (int nt = 0; nt < 4; nt++)
                    mma16816(acc[mt][nt], a[mt], b[nt]);
            // A lo frags, B hi again: Alo * Whi
#pragma unroll
            for (int mt = 0; mt < 4; mt++)
                ldsm_x4(a[mt], sAl_u + aoff + mt * (16*SROW*2) + kb);
#pragma unroll
            for (int ng = 0; ng < 2; ng++) {
                ldsm_x4(t4, sBh_u + boff + ng * (16*SROW*2) + kb);
                b[2*ng][0]   = t4[0]; b[2*ng][1]   = t4[2];
                b[2*ng+1][0] = t4[1]; b[2*ng+1][1] = t4[3];
            }
#pragma unroll
            for (int mt = 0; mt < 4; mt++)
#pragma unroll
                for (int nt = 0; nt < 4; nt++)
                    mma16816(acc[mt][nt], a[mt], b[nt]);
        }
    }

    // ---- epilogue ----
    const int grp = lane >> 2, cpair = (lane & 3) * 2;
#pragma unroll
    for (int mt = 0; mt < 4; mt++) {
#pragma unroll
        for (int half = 0; half < 2; half++) {
            const int m = m0 + warpM*64 + mt*16 + grp + half*8;
            const int bb = m >> 11, ss = m & 2047;
#pragma unroll
            for (int nt = 0; nt < 4; nt++) {
                float v0 = acc[mt][nt][half*2 + 0];
                float v1 = acc[mt][nt][half*2 + 1];
                const int ncol = n0 + warpN*32 + nt*8 + cpair;
                if (MODE == 0) {
                    const int sect = ncol >> 10;
                    const int cis  = ncol & 1023;
                    const int h = cis >> 6, d0 = cis & 63;
                    float* dstb = (sect == 0) ? g_q : (sect == 1) ? g_k : g_v;
                    float* dst = dstb + (((size_t)(bb*HEADS + h) * S_LEN + ss) * HD + d0);
                    if (sect == 2) {
                        *(float2*)dst = make_float2(v0, v1);
                    } else {
                        float cc = g_cos[ss*32 + (d0 >> 1)];
                        float sn = g_sin[ss*32 + (d0 >> 1)];
                        *(float2*)dst = make_float2(v0*cc - v1*sn, v0*sn + v1*cc);
                    }
                } else {
                    *(float2*)(C + (size_t)m * 1024 + ncol) = make_float2(v0, v1);
                }
            }
        }
    }
}

// ================= flash attention (fp32, verified in R1) =================
__global__ __launch_bounds__(128) void attn_kernel(const int* __restrict__ pm) {
    extern __shared__ float sm[];
    float* Qt = sm;
    float* KP = sm + 64*LDT;
    float* Vs = sm + 2*64*LDT;

    int qt = (int)gridDim.x - 1 - (int)blockIdx.x;
    int bh = blockIdx.y;
    int b  = bh >> 4;
    int h  = bh & 15;
    int tid = threadIdx.x;
    int tx = tid & 15;
    int ty = tid >> 4;

    const float* qbase = g_q + (size_t)bh * (S_LEN*HD);
    const float* kbase = g_k + (size_t)bh * (S_LEN*HD);
    const float* vbase = g_v + (size_t)bh * (S_LEN*HD);
    const int*   pmb   = pm + b * S_LEN;

    for (int idx = tid; idx < 64*64; idx += 128) {
        int d = idx & 63, r = idx >> 6;
        Qt[d*LDT + r] = qbase[(qt*64 + r)*HD + d];
    }

    float m_i[8], l_i[8], o[8][4];
#pragma unroll
    for (int i = 0; i < 8; i++) {
        m_i[i] = -1e30f; l_i[i] = 0.f;
#pragma unroll
        for (int j = 0; j < 4; j++) o[i][j] = 0.f;
    }

    for (int kt = 0; kt <= qt; kt++) {
        __syncthreads();
        for (int idx = tid; idx < 64*64; idx += 128) {
            int d = idx & 63, r = idx >> 6;
            int g = (kt*64 + r)*HD + d;
            KP[d*LDT + r] = kbase[g];
            Vs[r*LDT + d] = vbase[g];
        }
        __syncthreads();

        float sc[8][4];
#pragma unroll
        for (int i = 0; i < 8; i++)
#pragma unroll
            for (int j = 0; j < 4; j++) sc[i][j] = 0.f;

#pragma unroll 8
        for (int k = 0; k < 64; k++) {
            float4 q0 = *(const float4*)&Qt[k*LDT + ty*8];
            float4 q1 = *(const float4*)&Qt[k*LDT + ty*8 + 4];
            float4 kv = *(const float4*)&KP[k*LDT + tx*4];
            float qa[8] = {q0.x,q0.y,q0.z,q0.w,q1.x,q1.y,q1.z,q1.w};
            float kb[4] = {kv.x,kv.y,kv.z,kv.w};
#pragma unroll
            for (int i = 0; i < 8; i++)
#pragma unroll
                for (int j = 0; j < 4; j++)
                    sc[i][j] += qa[i] * kb[j];
        }

        int kg[4], pmask[4];
#pragma unroll
        for (int j = 0; j < 4; j++) {
            kg[j] = kt*64 + tx*4 + j;
            pmask[j] = pmb[kg[j]];
        }
#pragma unroll
        for (int i = 0; i < 8; i++) {
            int qg = qt*64 + ty*8 + i;
#pragma unroll
            for (int j = 0; j < 4; j++) {
                float v = sc[i][j] * 0.125f;
                if (kg[j] > qg || pmask[j] == 0) v = -1e30f;
                sc[i][j] = v;
            }
        }

#pragma unroll
        for (int i = 0; i < 8; i++) {
            float tmax = fmaxf(fmaxf(sc[i][0], sc[i][1]), fmaxf(sc[i][2], sc[i][3]));
#pragma unroll
            for (int off = 8; off >= 1; off >>= 1)
                tmax = fmaxf(tmax, __shfl_xor_sync(0xffffffffu, tmax, off));
            float mn = fmaxf(m_i[i], tmax);
            float psum = 0.f;
#pragma unroll
            for (int j = 0; j < 4; j++) {
                float p = (sc[i][j] > -1e29f) ? __expf(sc[i][j] - mn) : 0.f;
                sc[i][j] = p;
                psum += p;
            }
#pragma unroll
            for (int off = 8; off >= 1; off >>= 1)
                psum += __shfl_xor_sync(0xffffffffu, psum, off);
            float alpha = (m_i[i] > -1e29f) ? __expf(m_i[i] - mn) : 0.f;
            l_i[i] = l_i[i] * alpha + psum;
            m_i[i] = mn;
#pragma unroll
            for (int j = 0; j < 4; j++) o[i][j] *= alpha;
        }

        __syncthreads();
#pragma unroll
        for (int j = 0; j < 4; j++) {
            float4 p0 = make_float4(sc[0][j], sc[1][j], sc[2][j], sc[3][j]);
            float4 p1 = make_float4(sc[4][j], sc[5][j], sc[6][j], sc[7][j]);
            *(float4*)&KP[(tx*4 + j)*LDT + ty*8]     = p0;
            *(float4*)&KP[(tx*4 + j)*LDT + ty*8 + 4] = p1;
        }
        __syncthreads();

#pragma unroll 8
        for (int k = 0; k < 64; k++) {
            float4 p0 = *(const float4*)&KP[k*LDT + ty*8];
            float4 p1 = *(const float4*)&KP[k*LDT + ty*8 + 4];
            float4 vv = *(const float4*)&Vs[k*LDT + tx*4];
            float pa[8] = {p0.x,p0.y,p0.z,p0.w,p1.x,p1.y,p1.z,p1.w};
            float vb[4] = {vv.x,vv.y,vv.z,vv.w};
#pragma unroll
            for (int i = 0; i < 8; i++)
#pragma unroll
                for (int j = 0; j < 4; j++)
                    o[i][j] += pa[i] * vb[j];
        }
    }

#pragma unroll
    for (int i = 0; i < 8; i++) {
        float inv = 1.f / l_i[i];
        int srow = qt*64 + ty*8 + i;
        float* dst = g_att + ((size_t)(b*S_LEN + srow)*HEADS + h)*HD + tx*4;
#pragma unroll
        for (int j = 0; j < 4; j++) dst[j] = o[i][j] * inv;
    }
}

extern "C" void kernel_launch(void* const* d_in, const int* in_sizes, int n_in,
                              void* d_out, int out_size) {
    const float* x     = (const float*)d_in[0];
    const int*   pmask = (const int*)  d_in[1];
    const float* w_qkv = (const float*)d_in[2];
    const float* w_o   = (const float*)d_in[3];
    float* out = (float*)d_out;

    const int attn_smem = 3 * 64 * LDT * 4;
    cudaFuncSetAttribute(attn_kernel, cudaFuncAttributeMaxDynamicSharedMemorySize, attn_smem);
    cudaFuncSetAttribute(mma_gemm<0>, cudaFuncAttributeMaxDynamicSharedMemorySize, GEMM_SMEM);
    cudaFuncSetAttribute(mma_gemm<1>, cudaFuncAttributeMaxDynamicSharedMemorySize, GEMM_SMEM);

    rope_init_kernel<<<64, 1024>>>();
    conv_kernel<0><<<(BATCH*S_LEN*DMODEL/4 + 255)/256, 256>>>(x);
    conv_kernel<1><<<(3*DMODEL*DMODEL/4 + 255)/256, 256>>>(w_qkv);
    conv_kernel<2><<<(DMODEL*DMODEL/4 + 255)/256, 256>>>(w_o);
    mma_gemm<0><<<dim3(24, 64), 256, GEMM_SMEM>>>(nullptr);
    attn_kernel<<<dim3(32, 64), 128, attn_smem>>>(pmask);
    conv_kernel<3><<<(BATCH*S_LEN*DMODEL/4 + 255)/256, 256>>>(nullptr);
    mma_gemm<1><<<dim3(8, 64), 256, GEMM_SMEM>>>(out);
}

// round 5
// speedup vs baseline: 2.3258x; 1.5339x over previous
#include <cuda_runtime.h>
#include <cuda_bf16.h>
#include <math.h>
#include <stdint.h>

#define S_LEN   2048
#define BATCH   4
#define HEADS   16
#define HD      64
#define DMODEL  1024
#define SROW    40   // GEMM smem stride (bf16)
#define SR      72   // attention smem stride (bf16): 144B rows, ldmatrix conflict-free

// -------- device-global scratch --------
__device__ float g_att[BATCH*S_LEN*DMODEL];
__device__ float g_cos[S_LEN*(HD/2)];
__device__ float g_sin[S_LEN*(HD/2)];
__device__ __nv_bfloat16 g_xhi[BATCH*S_LEN*DMODEL];
__device__ __nv_bfloat16 g_xlo[BATCH*S_LEN*DMODEL];
__device__ __nv_bfloat16 g_whi[3*DMODEL*DMODEL];
__device__ __nv_bfloat16 g_wlo[3*DMODEL*DMODEL];
__device__ __nv_bfloat16 g_wohi[DMODEL*DMODEL];
__device__ __nv_bfloat16 g_wolo[DMODEL*DMODEL];
__device__ __nv_bfloat16 g_atthi[BATCH*S_LEN*DMODEL];
__device__ __nv_bfloat16 g_attlo[BATCH*S_LEN*DMODEL];
// bf16 hi/lo Q,K,V in [B*H][S][64]
__device__ __nv_bfloat16 g_qh[BATCH*HEADS*S_LEN*HD];
__device__ __nv_bfloat16 g_ql[BATCH*HEADS*S_LEN*HD];
__device__ __nv_bfloat16 g_kh[BATCH*HEADS*S_LEN*HD];
__device__ __nv_bfloat16 g_kl[BATCH*HEADS*S_LEN*HD];
__device__ __nv_bfloat16 g_vh[BATCH*HEADS*S_LEN*HD];
__device__ __nv_bfloat16 g_vl[BATCH*HEADS*S_LEN*HD];

// ================= PTX helpers =================
__device__ __forceinline__ uint32_t smem_u32(const void* p) {
    uint32_t a;
    asm("{ .reg .u64 t; cvta.to.shared.u64 t, %1; cvt.u32.u64 %0, t; }" : "=r"(a) : "l"(p));
    return a;
}
__device__ __forceinline__ void ldsm_x4(uint32_t* r, uint32_t addr) {
    asm volatile("ldmatrix.sync.aligned.m8n8.x4.shared.b16 {%0,%1,%2,%3}, [%4];"
        : "=r"(r[0]), "=r"(r[1]), "=r"(r[2]), "=r"(r[3]) : "r"(addr));
}
__device__ __forceinline__ void ldsm_x4_t(uint32_t* r, uint32_t addr) {
    asm volatile("ldmatrix.sync.aligned.m8n8.x4.trans.shared.b16 {%0,%1,%2,%3}, [%4];"
        : "=r"(r[0]), "=r"(r[1]), "=r"(r[2]), "=r"(r[3]) : "r"(addr));
}
__device__ __forceinline__ void mma16816(float* d, const uint32_t* a, const uint32_t* b) {
    asm volatile("mma.sync.aligned.m16n8k16.row.col.f32.bf16.bf16.f32 "
        "{%0,%1,%2,%3}, {%4,%5,%6,%7}, {%8,%9}, {%0,%1,%2,%3};"
        : "+f"(d[0]), "+f"(d[1]), "+f"(d[2]), "+f"(d[3])
        : "r"(a[0]), "r"(a[1]), "r"(a[2]), "r"(a[3]), "r"(b[0]), "r"(b[1]));
}
__device__ __forceinline__ uint32_t packbf(float a, float b) {
    __nv_bfloat162 t = __floats2bfloat162_rn(a, b);
    return *(uint32_t*)&t;
}

// ================= RoPE table =================
__global__ void rope_init_kernel() {
    int idx = blockIdx.x * blockDim.x + threadIdx.x;
    if (idx >= S_LEN * (HD/2)) return;
    int s = idx >> 5;
    int i = idx & 31;
    double freq = pow(10000.0, -2.0 * (double)i / (double)HD);
    double ang  = (double)s * freq;
    g_cos[idx] = (float)cos(ang);
    g_sin[idx] = (float)sin(ang);
}

// ================= fp32 -> bf16 hi/lo split =================
template<int WHICH>
__global__ __launch_bounds__(256) void conv_kernel(const float* __restrict__ srcp) {
    constexpr int n = (WHICH == 0) ? BATCH*S_LEN*DMODEL :
                      (WHICH == 1) ? 3*DMODEL*DMODEL :
                      (WHICH == 2) ? DMODEL*DMODEL : BATCH*S_LEN*DMODEL;
    const float* src = (WHICH == 3) ? (const float*)g_att : srcp;
    __nv_bfloat16* hi = (WHICH == 0) ? g_xhi : (WHICH == 1) ? g_whi :
                        (WHICH == 2) ? g_wohi : g_atthi;
    __nv_bfloat16* lo = (WHICH == 0) ? g_xlo : (WHICH == 1) ? g_wlo :
                        (WHICH == 2) ? g_wolo : g_attlo;
    int i = (blockIdx.x * blockDim.x + threadIdx.x) * 4;
    if (i >= n) return;
    float4 v = *(const float4*)(src + i);
    float vv[4] = {v.x, v.y, v.z, v.w};
    uint32_t hp[2], lp[2];
#pragma unroll
    for (int j = 0; j < 2; j++) {
        __nv_bfloat16 h0 = __float2bfloat16(vv[2*j]);
        __nv_bfloat16 h1 = __float2bfloat16(vv[2*j+1]);
        __nv_bfloat16 l0 = __float2bfloat16(vv[2*j]   - __bfloat162float(h0));
        __nv_bfloat16 l1 = __float2bfloat16(vv[2*j+1] - __bfloat162float(h1));
        hp[j] = (uint32_t)__bfloat16_as_ushort(h0) | ((uint32_t)__bfloat16_as_ushort(h1) << 16);
        lp[j] = (uint32_t)__bfloat16_as_ushort(l0) | ((uint32_t)__bfloat16_as_ushort(l1) << 16);
    }
    *(uint2*)(hi + i) = make_uint2(hp[0], hp[1]);
    *(uint2*)(lo + i) = make_uint2(lp[0], lp[1]);
}

// ================= mma.sync split-bf16 GEMM (R4-verified) =================
#define GEMM_SMEM (4 * 128 * SROW * 2)   // 40960 B
template<int MODE>
__global__ __launch_bounds__(256, 2) void mma_gemm(float* __restrict__ C) {
    extern __shared__ __nv_bfloat16 smb[];
    __nv_bfloat16* sAh = smb;
    __nv_bfloat16* sAl = smb + 128*SROW;
    __nv_bfloat16* sBh = smb + 2*128*SROW;
    __nv_bfloat16* sBl = smb + 3*128*SROW;

    const __nv_bfloat16* Ahi = (MODE == 0) ? g_xhi : g_atthi;
    const __nv_bfloat16* Alo = (MODE == 0) ? g_xlo : g_attlo;
    const __nv_bfloat16* Whi = (MODE == 0) ? g_whi : g_wohi;
    const __nv_bfloat16* Wlo = (MODE == 0) ? g_wlo : g_wolo;

    const int tid = threadIdx.x, lane = tid & 31, wid = tid >> 5;
    const int warpM = wid & 1, warpN = wid >> 1;
    const int m0 = blockIdx.y * 128, n0 = blockIdx.x * 128;

    const int lrow = tid >> 2;
    const int lkg  = (tid & 3) * 8;
    const size_t gA0 = (size_t)(m0 + lrow) * 1024 + lkg;
    const size_t gA1 = (size_t)(m0 + 64 + lrow) * 1024 + lkg;
    const size_t gB0 = (size_t)(n0 + lrow) * 1024 + lkg;
    const size_t gB1 = (size_t)(n0 + 64 + lrow) * 1024 + lkg;
    const int s0 = lrow * SROW + lkg;
    const int s1 = (64 + lrow) * SROW + lkg;

    const uint32_t sAh_u = smem_u32(sAh), sAl_u = smem_u32(sAl);
    const uint32_t sBh_u = smem_u32(sBh), sBl_u = smem_u32(sBl);
    const uint32_t lr = lane & 15, lc = (lane >> 4) * 8;
    const uint32_t aoff = ((warpM*64 + lr) * SROW + lc) * 2;
    const uint32_t boff = ((warpN*32 + lr) * SROW + lc) * 2;

    float acc[4][4][4];
#pragma unroll
    for (int i = 0; i < 4; i++)
#pragma unroll
        for (int j = 0; j < 4; j++)
#pragma unroll
            for (int t = 0; t < 4; t++) acc[i][j][t] = 0.f;

    for (int k0 = 0; k0 < 1024; k0 += 32) {
        __syncthreads();
        *(uint4*)(sAh + s0) = *(const uint4*)(Ahi + gA0 + k0);
        *(uint4*)(sAh + s1) = *(const uint4*)(Ahi + gA1 + k0);
        *(uint4*)(sAl + s0) = *(const uint4*)(Alo + gA0 + k0);
        *(uint4*)(sAl + s1) = *(const uint4*)(Alo + gA1 + k0);
        *(uint4*)(sBh + s0) = *(const uint4*)(Whi + gB0 + k0);
        *(uint4*)(sBh + s1) = *(const uint4*)(Whi + gB1 + k0);
        *(uint4*)(sBl + s0) = *(const uint4*)(Wlo + gB0 + k0);
        *(uint4*)(sBl + s1) = *(const uint4*)(Wlo + gB1 + k0);
        __syncthreads();

#pragma unroll
        for (int k16 = 0; k16 < 2; k16++) {
            const uint32_t kb = k16 * 32;
            uint32_t a[4][4], b[4][2], t4[4];
#pragma unroll
            for (int mt = 0; mt < 4; mt++)
                ldsm_x4(a[mt], sAh_u + aoff + mt * (16*SROW*2) + kb);
#pragma unroll
            for (int ng = 0; ng < 2; ng++) {
                ldsm_x4(t4, sBh_u + boff + ng * (16*SROW*2) + kb);
                b[2*ng][0]   = t4[0]; b[2*ng][1]   = t4[2];
                b[2*ng+1][0] = t4[1]; b[2*ng+1][1] = t4[3];
            }
#pragma unroll
            for (int mt = 0; mt < 4; mt++)
#pragma unroll
                for (int nt = 0; nt < 4; nt++)
                    mma16816(acc[mt][nt], a[mt], b[nt]);
#pragma unroll
            for (int ng = 0; ng < 2; ng++) {
                ldsm_x4(t4, sBl_u + boff + ng * (16*SROW*2) + kb);
                b[2*ng][0]   = t4[0]; b[2*ng][1]   = t4[2];
                b[2*ng+1][0] = t4[1]; b[2*ng+1][1] = t4[3];
            }
#pragma unroll
            for (int mt = 0; mt < 4; mt++)
#pragma unroll
                for (int nt = 0; nt < 4; nt++)
                    mma16816(acc[mt][nt], a[mt], b[nt]);
#pragma unroll
            for (int mt = 0; mt < 4; mt++)
                ldsm_x4(a[mt], sAl_u + aoff + mt * (16*SROW*2) + kb);
#pragma unroll
            for (int ng = 0; ng < 2; ng++) {
                ldsm_x4(t4, sBh_u + boff + ng * (16*SROW*2) + kb);
                b[2*ng][0]   = t4[0]; b[2*ng][1]   = t4[2];
                b[2*ng+1][0] = t4[1]; b[2*ng+1][1] = t4[3];
            }
#pragma unroll
            for (int mt = 0; mt < 4; mt++)
#pragma unroll
                for (int nt = 0; nt < 4; nt++)
                    mma16816(acc[mt][nt], a[mt], b[nt]);
        }
    }

    // ---- epilogue ----
    const int grp = lane >> 2, cpair = (lane & 3) * 2;
#pragma unroll
    for (int mt = 0; mt < 4; mt++) {
#pragma unroll
        for (int half = 0; half < 2; half++) {
            const int m = m0 + warpM*64 + mt*16 + grp + half*8;
            const int bb = m >> 11, ss = m & 2047;
#pragma unroll
            for (int nt = 0; nt < 4; nt++) {
                float v0 = acc[mt][nt][half*2 + 0];
                float v1 = acc[mt][nt][half*2 + 1];
                const int ncol = n0 + warpN*32 + nt*8 + cpair;
                if (MODE == 0) {
                    const int sect = ncol >> 10;
                    const int cis  = ncol & 1023;
                    const int h = cis >> 6, d0 = cis & 63;
                    const size_t di = ((size_t)(bb*HEADS + h) * S_LEN + ss) * HD + d0;
                    if (sect != 2) {
                        float cc = g_cos[ss*32 + (d0 >> 1)];
                        float sn = g_sin[ss*32 + (d0 >> 1)];
                        float r0 = v0*cc - v1*sn;
                        float r1 = v0*sn + v1*cc;
                        v0 = r0; v1 = r1;
                    }
                    __nv_bfloat16 h0 = __float2bfloat16(v0);
                    __nv_bfloat16 h1 = __float2bfloat16(v1);
                    __nv_bfloat16 l0 = __float2bfloat16(v0 - __bfloat162float(h0));
                    __nv_bfloat16 l1 = __float2bfloat16(v1 - __bfloat162float(h1));
                    __nv_bfloat16* dh = (sect == 0) ? g_qh : (sect == 1) ? g_kh : g_vh;
                    __nv_bfloat16* dl = (sect == 0) ? g_ql : (sect == 1) ? g_kl : g_vl;
                    *(__nv_bfloat162*)(dh + di) = __nv_bfloat162(h0, h1);
                    *(__nv_bfloat162*)(dl + di) = __nv_bfloat162(l0, l1);
                } else {
                    *(float2*)(C + (size_t)m * 1024 + ncol) = make_float2(v0, v1);
                }
            }
        }
    }
}

// ================= mma.sync flash attention =================
// BQ=64 (4 warps x 16 rows), BK=64, hd=64, split-bf16 both GEMMs.
#define ATTN_SMEM (6*64*SR*2 + 256)
__global__ __launch_bounds__(128) void attn_mma(const int* __restrict__ pm) {
    extern __shared__ __nv_bfloat16 smb[];
    __nv_bfloat16* sQh = smb;
    __nv_bfloat16* sQl = smb + 1*64*SR;
    __nv_bfloat16* sKh = smb + 2*64*SR;
    __nv_bfloat16* sKl = smb + 3*64*SR;
    __nv_bfloat16* sVh = smb + 4*64*SR;
    __nv_bfloat16* sVl = smb + 5*64*SR;
    int* spm = (int*)(smb + 6*64*SR);

    const int qt = (int)gridDim.x - 1 - (int)blockIdx.x;
    const int bh = blockIdx.y;
    const int b  = bh >> 4;
    const int tid = threadIdx.x, lane = tid & 31, w = tid >> 5;
    const size_t base = (size_t)bh * S_LEN * HD;
    const int* pmb = pm + b * S_LEN;

    // load Q tile (64 x 64 bf16, hi+lo)
#pragma unroll
    for (int i = tid; i < 512; i += 128) {
        int row = i >> 3, c8 = (i & 7) * 8;
        *(uint4*)(sQh + row*SR + c8) = *(const uint4*)(g_qh + base + (size_t)(qt*64 + row)*HD + c8);
        *(uint4*)(sQl + row*SR + c8) = *(const uint4*)(g_ql + base + (size_t)(qt*64 + row)*HD + c8);
    }
    __syncthreads();

    const uint32_t sQh_u = smem_u32(sQh), sQl_u = smem_u32(sQl);
    const uint32_t sKh_u = smem_u32(sKh), sKl_u = smem_u32(sKl);
    const uint32_t sVh_u = smem_u32(sVh), sVl_u = smem_u32(sVl);
    const uint32_t lr = lane & 15, lc = lane >> 4;
    const uint32_t qoff = ((w*16 + lr)*SR + lc*8) * 2;

    uint32_t Qh[4][4], Ql[4][4];
#pragma unroll
    for (int kc = 0; kc < 4; kc++) {
        ldsm_x4(Qh[kc], sQh_u + qoff + kc*32);
        ldsm_x4(Ql[kc], sQl_u + qoff + kc*32);
    }

    float o[8][4];
#pragma unroll
    for (int i = 0; i < 8; i++)
#pragma unroll
        for (int j = 0; j < 4; j++) o[i][j] = 0.f;
    float mrow[2] = {-1e30f, -1e30f}, lrow[2] = {0.f, 0.f};

    const int grp = lane >> 2, cp = (lane & 3) * 2;
    // trans-ldmatrix address components for V
    const uint32_t vrow = (lane & 7) + (lane & 8);
    const uint32_t vcol = (lane & 16) ? 8 : 0;

    for (int kt = 0; kt <= qt; kt++) {
        __syncthreads();
#pragma unroll
        for (int i = tid; i < 512; i += 128) {
            int row = i >> 3, c8 = (i & 7) * 8;
            size_t g = base + (size_t)(kt*64 + row)*HD + c8;
            *(uint4*)(sKh + row*SR + c8) = *(const uint4*)(g_kh + g);
            *(uint4*)(sKl + row*SR + c8) = *(const uint4*)(g_kl + g);
            *(uint4*)(sVh + row*SR + c8) = *(const uint4*)(g_vh + g);
            *(uint4*)(sVl + row*SR + c8) = *(const uint4*)(g_vl + g);
        }
        if (tid < 64) spm[tid] = pmb[kt*64 + tid];
        __syncthreads();

        // ---- scores: S = Q K^T (split: QhKh + QhKl + QlKh) ----
        float sc[8][4];
#pragma unroll
        for (int i = 0; i < 8; i++)
#pragma unroll
            for (int j = 0; j < 4; j++) sc[i][j] = 0.f;

        uint32_t bfr[8][2], t4[4];
#pragma unroll
        for (int kc = 0; kc < 4; kc++) {
#pragma unroll
            for (int ng = 0; ng < 4; ng++) {
                ldsm_x4(t4, sKh_u + ((ng*16 + lr)*SR + kc*16 + lc*8)*2);
                bfr[2*ng][0]   = t4[0]; bfr[2*ng][1]   = t4[2];
                bfr[2*ng+1][0] = t4[1]; bfr[2*ng+1][1] = t4[3];
            }
#pragma unroll
            for (int nt = 0; nt < 8; nt++) mma16816(sc[nt], Qh[kc], bfr[nt]);
        }
#pragma unroll
        for (int kc = 0; kc < 4; kc++) {
#pragma unroll
            for (int ng = 0; ng < 4; ng++) {
                ldsm_x4(t4, sKl_u + ((ng*16 + lr)*SR + kc*16 + lc*8)*2);
                bfr[2*ng][0]   = t4[0]; bfr[2*ng][1]   = t4[2];
                bfr[2*ng+1][0] = t4[1]; bfr[2*ng+1][1] = t4[3];
            }
#pragma unroll
            for (int nt = 0; nt < 8; nt++) mma16816(sc[nt], Qh[kc], bfr[nt]);
        }
#pragma unroll
        for (int kc = 0; kc < 4; kc++) {
#pragma unroll
            for (int ng = 0; ng < 4; ng++) {
                ldsm_x4(t4, sKh_u + ((ng*16 + lr)*SR + kc*16 + lc*8)*2);
                bfr[2*ng][0]   = t4[0]; bfr[2*ng][1]   = t4[2];
                bfr[2*ng+1][0] = t4[1]; bfr[2*ng+1][1] = t4[3];
            }
#pragma unroll
            for (int nt = 0; nt < 8; nt++) mma16816(sc[nt], Ql[kc], bfr[nt]);
        }

        // ---- scale + causal + padding mask ----
#pragma unroll
        for (int nt = 0; nt < 8; nt++) {
            int key0 = kt*64 + nt*8 + cp;
            int p0 = spm[nt*8 + cp], p1 = spm[nt*8 + cp + 1];
#pragma unroll
            for (int h = 0; h < 2; h++) {
                int q = qt*64 + w*16 + grp + h*8;
                float s0 = sc[nt][2*h]   * 0.125f;
                float s1 = sc[nt][2*h+1] * 0.125f;
                if (key0 > q     || p0 == 0) s0 = -1e30f;
                if (key0 + 1 > q || p1 == 0) s1 = -1e30f;
                sc[nt][2*h]   = s0;
                sc[nt][2*h+1] = s1;
            }
        }

        // ---- online softmax ----
#pragma unroll
        for (int h = 0; h < 2; h++) {
            float vmax = -1e30f;
#pragma unroll
            for (int nt = 0; nt < 8; nt++)
                vmax = fmaxf(vmax, fmaxf(sc[nt][2*h], sc[nt][2*h+1]));
            vmax = fmaxf(vmax, __shfl_xor_sync(0xffffffffu, vmax, 1));
            vmax = fmaxf(vmax, __shfl_xor_sync(0xffffffffu, vmax, 2));
            float mn = fmaxf(mrow[h], vmax);
            float psum = 0.f;
#pragma unroll
            for (int nt = 0; nt < 8; nt++) {
                float p0 = __expf(sc[nt][2*h]   - mn);
                float p1 = __expf(sc[nt][2*h+1] - mn);
                sc[nt][2*h] = p0; sc[nt][2*h+1] = p1;
                psum += p0 + p1;
            }
            psum += __shfl_xor_sync(0xffffffffu, psum, 1);
            psum += __shfl_xor_sync(0xffffffffu, psum, 2);
            float alpha = __expf(mrow[h] - mn);
            lrow[h] = lrow[h] * alpha + psum;
            mrow[h] = mn;
#pragma unroll
            for (int nt = 0; nt < 8; nt++) {
                o[nt][2*h]   *= alpha;
                o[nt][2*h+1] *= alpha;
            }
        }

        // ---- pack P into A-fragments (hi/lo) ----
        uint32_t Ph[4][4], Pl[4][4];
#pragma unroll
        for (int kc = 0; kc < 4; kc++) {
            const int t0 = 2*kc, t1 = 2*kc + 1;
            float hv[8], lv[8];
#pragma unroll
            for (int e = 0; e < 4; e++) {
                float p0 = sc[t0][e], p1 = sc[t1][e];
                float h0 = __bfloat162float(__float2bfloat16(p0));
                float h1 = __bfloat162float(__float2bfloat16(p1));
                hv[e] = h0; hv[4+e] = h1;
                lv[e] = p0 - h0; lv[4+e] = p1 - h1;
            }
            Ph[kc][0] = packbf(hv[0], hv[1]); Ph[kc][1] = packbf(hv[2], hv[3]);
            Ph[kc][2] = packbf(hv[4], hv[5]); Ph[kc][3] = packbf(hv[6], hv[7]);
            Pl[kc][0] = packbf(lv[0], lv[1]); Pl[kc][1] = packbf(lv[2], lv[3]);
            Pl[kc][2] = packbf(lv[4], lv[5]); Pl[kc][3] = packbf(lv[6], lv[7]);
        }

        // ---- PV: O += P V (split: PhVh + PhVl + PlVh) ----
#pragma unroll
        for (int kc = 0; kc < 4; kc++) {
#pragma unroll
            for (int ngp = 0; ngp < 4; ngp++) {
                uint32_t addr = sVh_u + ((kc*16 + vrow)*SR + ngp*16 + vcol)*2;
                ldsm_x4_t(t4, addr);
                uint32_t b0[2] = {t4[0], t4[1]}, b1[2] = {t4[2], t4[3]};
                mma16816(o[2*ngp],   Ph[kc], b0);
                mma16816(o[2*ngp+1], Ph[kc], b1);
            }
        }
#pragma unroll
        for (int kc = 0; kc < 4; kc++) {
#pragma unroll
            for (int ngp = 0; ngp < 4; ngp++) {
                uint32_t addr = sVl_u + ((kc*16 + vrow)*SR + ngp*16 + vcol)*2;
                ldsm_x4_t(t4, addr);
                uint32_t b0[2] = {t4[0], t4[1]}, b1[2] = {t4[2], t4[3]};
                mma16816(o[2*ngp],   Ph[kc], b0);
                mma16816(o[2*ngp+1], Ph[kc], b1);
            }
        }
#pragma unroll
        for (int kc = 0; kc < 4; kc++) {
#pragma unroll
            for (int ngp = 0; ngp < 4; ngp++) {
                uint32_t addr = sVh_u + ((kc*16 + vrow)*SR + ngp*16 + vcol)*2;
                ldsm_x4_t(t4, addr);
                uint32_t b0[2] = {t4[0], t4[1]}, b1[2] = {t4[2], t4[3]};
                mma16816(o[2*ngp],   Pl[kc], b0);
                mma16816(o[2*ngp+1], Pl[kc], b1);
            }
        }
    }

    // ---- finalize: write [B,S,H,hd] fp32 ----
    const int h_ = bh & 15;
#pragma unroll
    for (int hf = 0; hf < 2; hf++) {
        float inv = 1.f / lrow[hf];
        int srow = qt*64 + w*16 + grp + hf*8;
        float* dst = g_att + ((size_t)(b*S_LEN + srow)*HEADS + h_)*HD;
#pragma unroll
        for (int nt = 0; nt < 8; nt++) {
            int d = nt*8 + cp;
            *(float2*)(dst + d) = make_float2(o[nt][2*hf]*inv, o[nt][2*hf+1]*inv);
        }
    }
}

extern "C" void kernel_launch(void* const* d_in, const int* in_sizes, int n_in,
                              void* d_out, int out_size) {
    const float* x     = (const float*)d_in[0];
    const int*   pmask = (const int*)  d_in[1];
    const float* w_qkv = (const float*)d_in[2];
    const float* w_o   = (const float*)d_in[3];
    float* out = (float*)d_out;

    cudaFuncSetAttribute(attn_mma, cudaFuncAttributeMaxDynamicSharedMemorySize, ATTN_SMEM);
    cudaFuncSetAttribute(mma_gemm<0>, cudaFuncAttributeMaxDynamicSharedMemorySize, GEMM_SMEM);
    cudaFuncSetAttribute(mma_gemm<1>, cudaFuncAttributeMaxDynamicSharedMemorySize, GEMM_SMEM);

    rope_init_kernel<<<64, 1024>>>();
    conv_kernel<0><<<(BATCH*S_LEN*DMODEL/4 + 255)/256, 256>>>(x);
    conv_kernel<1><<<(3*DMODEL*DMODEL/4 + 255)/256, 256>>>(w_qkv);
    conv_kernel<2><<<(DMODEL*DMODEL/4 + 255)/256, 256>>>(w_o);
    mma_gemm<0><<<dim3(24, 64), 256, GEMM_SMEM>>>(nullptr);
    attn_mma<<<dim3(32, 64), 128, ATTN_SMEM>>>(pmask);
    conv_kernel<3><<<(BATCH*S_LEN*DMODEL/4 + 255)/256, 256>>>(nullptr);
    mma_gemm<1><<<dim3(8, 64), 256, GEMM_SMEM>>>(out);
}

// round 7
// speedup vs baseline: 2.4562x; 1.0561x over previous
#include <cuda_runtime.h>
#include <cuda_bf16.h>
#include <math.h>
#include <stdint.h>

#define S_LEN   2048
#define BATCH   4
#define HEADS   16
#define HD      64
#define DMODEL  1024
#define SROW    40   // GEMM smem stride (bf16)
#define SR      72   // attention smem stride (bf16)

// -------- device-global scratch --------
__device__ float g_cos[S_LEN*(HD/2)];
__device__ float g_sin[S_LEN*(HD/2)];
__device__ __nv_bfloat16 g_xhi[BATCH*S_LEN*DMODEL];
__device__ __nv_bfloat16 g_xlo[BATCH*S_LEN*DMODEL];
__device__ __nv_bfloat16 g_whi[3*DMODEL*DMODEL];
__device__ __nv_bfloat16 g_wlo[3*DMODEL*DMODEL];
__device__ __nv_bfloat16 g_wohi[DMODEL*DMODEL];
__device__ __nv_bfloat16 g_wolo[DMODEL*DMODEL];
__device__ __nv_bfloat16 g_atthi[BATCH*S_LEN*DMODEL];
__device__ __nv_bfloat16 g_attlo[BATCH*S_LEN*DMODEL];
__device__ __nv_bfloat16 g_qh[BATCH*HEADS*S_LEN*HD];
__device__ __nv_bfloat16 g_ql[BATCH*HEADS*S_LEN*HD];
__device__ __nv_bfloat16 g_kh[BATCH*HEADS*S_LEN*HD];
__device__ __nv_bfloat16 g_kl[BATCH*HEADS*S_LEN*HD];
__device__ __nv_bfloat16 g_vh[BATCH*HEADS*S_LEN*HD];
__device__ __nv_bfloat16 g_vl[BATCH*HEADS*S_LEN*HD];

// ================= PTX helpers =================
__device__ __forceinline__ uint32_t smem_u32(const void* p) {
    uint32_t a;
    asm("{ .reg .u64 t; cvta.to.shared.u64 t, %1; cvt.u32.u64 %0, t; }" : "=r"(a) : "l"(p));
    return a;
}
__device__ __forceinline__ void ldsm_x4(uint32_t* r, uint32_t addr) {
    asm volatile("ldmatrix.sync.aligned.m8n8.x4.shared.b16 {%0,%1,%2,%3}, [%4];"
        : "=r"(r[0]), "=r"(r[1]), "=r"(r[2]), "=r"(r[3]) : "r"(addr));
}
__device__ __forceinline__ void ldsm_x4_t(uint32_t* r, uint32_t addr) {
    asm volatile("ldmatrix.sync.aligned.m8n8.x4.trans.shared.b16 {%0,%1,%2,%3}, [%4];"
        : "=r"(r[0]), "=r"(r[1]), "=r"(r[2]), "=r"(r[3]) : "r"(addr));
}
__device__ __forceinline__ void mma16816(float* d, const uint32_t* a, const uint32_t* b) {
    asm volatile("mma.sync.aligned.m16n8k16.row.col.f32.bf16.bf16.f32 "
        "{%0,%1,%2,%3}, {%4,%5,%6,%7}, {%8,%9}, {%0,%1,%2,%3};"
        : "+f"(d[0]), "+f"(d[1]), "+f"(d[2]), "+f"(d[3])
        : "r"(a[0]), "r"(a[1]), "r"(a[2]), "r"(a[3]), "r"(b[0]), "r"(b[1]));
}
__device__ __forceinline__ uint32_t packbf(float a, float b) {
    __nv_bfloat162 t = __floats2bfloat162_rn(a, b);
    return *(uint32_t*)&t;
}
__device__ __forceinline__ void cp16(uint32_t dst, const void* src) {
    asm volatile("cp.async.cg.shared.global [%0], [%1], 16;" :: "r"(dst), "l"(src));
}
__device__ __forceinline__ void cp_commit() {
    asm volatile("cp.async.commit_group;" ::: "memory");
}
template<int N>
__device__ __forceinline__ void cp_wait() {
    asm volatile("cp.async.wait_group %0;" :: "n"(N) : "memory");
}

// ================= RoPE table =================
__global__ void rope_init_kernel() {
    int idx = blockIdx.x * blockDim.x + threadIdx.x;
    if (idx >= S_LEN * (HD/2)) return;
    int s = idx >> 5;
    int i = idx & 31;
    double freq = pow(10000.0, -2.0 * (double)i / (double)HD);
    double ang  = (double)s * freq;
    g_cos[idx] = (float)cos(ang);
    g_sin[idx] = (float)sin(ang);
}

// ================= fp32 -> bf16 hi/lo split =================
template<int WHICH>
__global__ __launch_bounds__(256) void conv_kernel(const float* __restrict__ src) {
    constexpr int n = (WHICH == 0) ? BATCH*S_LEN*DMODEL :
                      (WHICH == 1) ? 3*DMODEL*DMODEL : DMODEL*DMODEL;
    __nv_bfloat16* hi = (WHICH == 0) ? g_xhi : (WHICH == 1) ? g_whi : g_wohi;
    __nv_bfloat16* lo = (WHICH == 0) ? g_xlo : (WHICH == 1) ? g_wlo : g_wolo;
    int i = (blockIdx.x * blockDim.x + threadIdx.x) * 4;
    if (i >= n) return;
    float4 v = *(const float4*)(src + i);
    float vv[4] = {v.x, v.y, v.z, v.w};
    uint32_t hp[2], lp[2];
#pragma unroll
    for (int j = 0; j < 2; j++) {
        __nv_bfloat16 h0 = __float2bfloat16(vv[2*j]);
        __nv_bfloat16 h1 = __float2bfloat16(vv[2*j+1]);
        __nv_bfloat16 l0 = __float2bfloat16(vv[2*j]   - __bfloat162float(h0));
        __nv_bfloat16 l1 = __float2bfloat16(vv[2*j+1] - __bfloat162float(h1));
        hp[j] = (uint32_t)__bfloat16_as_ushort(h0) | ((uint32_t)__bfloat16_as_ushort(h1) << 16);
        lp[j] = (uint32_t)__bfloat16_as_ushort(l0) | ((uint32_t)__bfloat16_as_ushort(l1) << 16);
    }
    *(uint2*)(hi + i) = make_uint2(hp[0], hp[1]);
    *(uint2*)(lo + i) = make_uint2(lp[0], lp[1]);
}

// ================= cp.async double-buffered split-bf16 GEMM =================
// Stage: 4 arrays x 128 rows x SROW bf16 = 40960 B. 2 stages.
#define STG_B   (4 * 128 * SROW * 2)
#define GEMM_SMEM (2 * STG_B)            // 81920 B
#define OFF_AL  (128 * SROW * 2)
#define OFF_BH  (2 * 128 * SROW * 2)
#define OFF_BL  (3 * 128 * SROW * 2)
template<int MODE>
__global__ __launch_bounds__(256, 2) void mma_gemm(float* __restrict__ C) {
    extern __shared__ __nv_bfloat16 smb[];
    const __nv_bfloat16* Ahi = (MODE == 0) ? g_xhi : g_atthi;
    const __nv_bfloat16* Alo = (MODE == 0) ? g_xlo : g_attlo;
    const __nv_bfloat16* Whi = (MODE == 0) ? g_whi : g_wohi;
    const __nv_bfloat16* Wlo = (MODE == 0) ? g_wlo : g_wolo;

    const int tid = threadIdx.x, lane = tid & 31, wid = tid >> 5;
    const int warpM = wid & 1, warpN = wid >> 1;
    const int m0 = blockIdx.y * 128, n0 = blockIdx.x * 128;

    const int lrow = tid >> 2;
    const int lkg  = (tid & 3) * 8;
    const size_t gA0 = (size_t)(m0 + lrow) * 1024 + lkg;
    const size_t gA1 = (size_t)(m0 + 64 + lrow) * 1024 + lkg;
    const size_t gB0 = (size_t)(n0 + lrow) * 1024 + lkg;
    const size_t gB1 = (size_t)(n0 + 64 + lrow) * 1024 + lkg;
    const uint32_t sb0 = (lrow * SROW + lkg) * 2;          // byte offset in stage
    const uint32_t sb1 = ((64 + lrow) * SROW + lkg) * 2;

    const uint32_t base_u = smem_u32(smb);
    const uint32_t lr = lane & 15, lc = (lane >> 4) * 8;
    const uint32_t aoff = ((warpM*64 + lr) * SROW + lc) * 2;
    const uint32_t boff = ((warpN*32 + lr) * SROW + lc) * 2;

    float acc[4][4][4];
#pragma unroll
    for (int i = 0; i < 4; i++)
#pragma unroll
        for (int j = 0; j < 4; j++)
#pragma unroll
            for (int t = 0; t < 4; t++) acc[i][j][t] = 0.f;

    auto prefetch = [&](int c, int stg) {
        const uint32_t sb = base_u + stg * STG_B;
        const int co = c * 32;
        cp16(sb + sb0,          Ahi + gA0 + co);
        cp16(sb + sb1,          Ahi + gA1 + co);
        cp16(sb + OFF_AL + sb0, Alo + gA0 + co);
        cp16(sb + OFF_AL + sb1, Alo + gA1 + co);
        cp16(sb + OFF_BH + sb0, Whi + gB0 + co);
        cp16(sb + OFF_BH + sb1, Whi + gB1 + co);
        cp16(sb + OFF_BL + sb0, Wlo + gB0 + co);
        cp16(sb + OFF_BL + sb1, Wlo + gB1 + co);
        cp_commit();
    };

    prefetch(0, 0);
    for (int c = 0; c < 32; c++) {
        const int stg = c & 1;
        if (c + 1 < 32) {
            prefetch(c + 1, stg ^ 1);
            cp_wait<1>();
        } else {
            cp_wait<0>();
        }
        __syncthreads();

        const uint32_t su = base_u + stg * STG_B;
#pragma unroll
        for (int k16 = 0; k16 < 2; k16++) {
            const uint32_t kb = k16 * 32;
            uint32_t a[4][4], b[4][2], t4[4];
#pragma unroll
            for (int mt = 0; mt < 4; mt++)
                ldsm_x4(a[mt], su + aoff + mt * (16*SROW*2) + kb);
#pragma unroll
            for (int ng = 0; ng < 2; ng++) {
                ldsm_x4(t4, su + OFF_BH + boff + ng * (16*SROW*2) + kb);
                b[2*ng][0]   = t4[0]; b[2*ng][1]   = t4[2];
                b[2*ng+1][0] = t4[1]; b[2*ng+1][1] = t4[3];
            }
#pragma unroll
            for (int mt = 0; mt < 4; mt++)
#pragma unroll
                for (int nt = 0; nt < 4; nt++)
                    mma16816(acc[mt][nt], a[mt], b[nt]);
#pragma unroll
            for (int ng = 0; ng < 2; ng++) {
                ldsm_x4(t4, su + OFF_BL + boff + ng * (16*SROW*2) + kb);
                b[2*ng][0]   = t4[0]; b[2*ng][1]   = t4[2];
                b[2*ng+1][0] = t4[1]; b[2*ng+1][1] = t4[3];
            }
#pragma unroll
            for (int mt = 0; mt < 4; mt++)
#pragma unroll
                for (int nt = 0; nt < 4; nt++)
                    mma16816(acc[mt][nt], a[mt], b[nt]);
#pragma unroll
            for (int mt = 0; mt < 4; mt++)
                ldsm_x4(a[mt], su + OFF_AL + aoff + mt * (16*SROW*2) + kb);
#pragma unroll
            for (int ng = 0; ng < 2; ng++) {
                ldsm_x4(t4, su + OFF_BH + boff + ng * (16*SROW*2) + kb);
                b[2*ng][0]   = t4[0]; b[2*ng][1]   = t4[2];
                b[2*ng+1][0] = t4[1]; b[2*ng+1][1] = t4[3];
            }
#pragma unroll
            for (int mt = 0; mt < 4; mt++)
#pragma unroll
                for (int nt = 0; nt < 4; nt++)
                    mma16816(acc[mt][nt], a[mt], b[nt]);
        }
        __syncthreads();
    }

    // ---- epilogue ----
    const int grp = lane >> 2, cpair = (lane & 3) * 2;
#pragma unroll
    for (int mt = 0; mt < 4; mt++) {
#pragma unroll
        for (int half = 0; half < 2; half++) {
            const int m = m0 + warpM*64 + mt*16 + grp + half*8;
            const int bb = m >> 11, ss = m & 2047;
#pragma unroll
            for (int nt = 0; nt < 4; nt++) {
                float v0 = acc[mt][nt][half*2 + 0];
                float v1 = acc[mt][nt][half*2 + 1];
                const int ncol = n0 + warpN*32 + nt*8 + cpair;
                if (MODE == 0) {
                    const int sect = ncol >> 10;
                    const int cis  = ncol & 1023;
                    const int h = cis >> 6, d0 = cis & 63;
                    const size_t di = ((size_t)(bb*HEADS + h) * S_LEN + ss) * HD + d0;
                    if (sect != 2) {
                        float cc = g_cos[ss*32 + (d0 >> 1)];
                        float sn = g_sin[ss*32 + (d0 >> 1)];
                        float r0 = v0*cc - v1*sn;
                        float r1 = v0*sn + v1*cc;
                        v0 = r0; v1 = r1;
                    }
                    __nv_bfloat16 h0 = __float2bfloat16(v0);
                    __nv_bfloat16 h1 = __float2bfloat16(v1);
                    __nv_bfloat16 l0 = __float2bfloat16(v0 - __bfloat162float(h0));
                    __nv_bfloat16 l1 = __float2bfloat16(v1 - __bfloat162float(h1));
                    __nv_bfloat16* dh = (sect == 0) ? g_qh : (sect == 1) ? g_kh : g_vh;
                    __nv_bfloat16* dl = (sect == 0) ? g_ql : (sect == 1) ? g_kl : g_vl;
                    *(__nv_bfloat162*)(dh + di) = __nv_bfloat162(h0, h1);
                    *(__nv_bfloat162*)(dl + di) = __nv_bfloat162(l0, l1);
                } else {
                    *(float2*)(C + (size_t)m * 1024 + ncol) = make_float2(v0, v1);
                }
            }
        }
    }
}

// ================= mma.sync flash attention (R5-verified) =================
#define ATTN_SMEM (6*64*SR*2 + 256)
__global__ __launch_bounds__(128) void attn_mma(const int* __restrict__ pm) {
    extern __shared__ __nv_bfloat16 smb[];
    __nv_bfloat16* sQh = smb;
    __nv_bfloat16* sQl = smb + 1*64*SR;
    __nv_bfloat16* sKh = smb + 2*64*SR;
    __nv_bfloat16* sKl = smb + 3*64*SR;
    __nv_bfloat16* sVh = smb + 4*64*SR;
    __nv_bfloat16* sVl = smb + 5*64*SR;
    int* spm = (int*)(smb + 6*64*SR);

    const int qt = (int)gridDim.x - 1 - (int)blockIdx.x;
    const int bh = blockIdx.y;
    const int b  = bh >> 4;
    const int tid = threadIdx.x, lane = tid & 31, w = tid >> 5;
    const size_t base = (size_t)bh * S_LEN * HD;
    const int* pmb = pm + b * S_LEN;

#pragma unroll
    for (int i = tid; i < 512; i += 128) {
        int row = i >> 3, c8 = (i & 7) * 8;
        *(uint4*)(sQh + row*SR + c8) = *(const uint4*)(g_qh + base + (size_t)(qt*64 + row)*HD + c8);
        *(uint4*)(sQl + row*SR + c8) = *(const uint4*)(g_ql + base + (size_t)(qt*64 + row)*HD + c8);
    }
    __syncthreads();

    const uint32_t sQh_u = smem_u32(sQh), sQl_u = smem_u32(sQl);
    const uint32_t sKh_u = smem_u32(sKh), sKl_u = smem_u32(sKl);
    const uint32_t sVh_u = smem_u32(sVh), sVl_u = smem_u32(sVl);
    const uint32_t lr = lane & 15, lc = lane >> 4;
    const uint32_t qoff = ((w*16 + lr)*SR + lc*8) * 2;

    uint32_t Qh[4][4], Ql[4][4];
#pragma unroll
    for (int kc = 0; kc < 4; kc++) {
        ldsm_x4(Qh[kc], sQh_u + qoff + kc*32);
        ldsm_x4(Ql[kc], sQl_u + qoff + kc*32);
    }

    float o[8][4];
#pragma unroll
    for (int i = 0; i < 8; i++)
#pragma unroll
        for (int j = 0; j < 4; j++) o[i][j] = 0.f;
    float mrow[2] = {-1e30f, -1e30f}, lrow[2] = {0.f, 0.f};

    const int grp = lane >> 2, cp = (lane & 3) * 2;
    const uint32_t vrow = (lane & 7) + (lane & 8);
    const uint32_t vcol = (lane & 16) ? 8 : 0;

    for (int kt = 0; kt <= qt; kt++) {
        __syncthreads();
#pragma unroll
        for (int i = tid; i < 512; i += 128) {
            int row = i >> 3, c8 = (i & 7) * 8;
            size_t g = base + (size_t)(kt*64 + row)*HD + c8;
            *(uint4*)(sKh + row*SR + c8) = *(const uint4*)(g_kh + g);
            *(uint4*)(sKl + row*SR + c8) = *(const uint4*)(g_kl + g);
            *(uint4*)(sVh + row*SR + c8) = *(const uint4*)(g_vh + g);
            *(uint4*)(sVl + row*SR + c8) = *(const uint4*)(g_vl + g);
        }
        if (tid < 64) spm[tid] = pmb[kt*64 + tid];
        __syncthreads();

        float sc[8][4];
#pragma unroll
        for (int i = 0; i < 8; i++)
#pragma unroll
            for (int j = 0; j < 4; j++) sc[i][j] = 0.f;

        uint32_t bfr[8][2], t4[4];
#pragma unroll
        for (int kc = 0; kc < 4; kc++) {
#pragma unroll
            for (int ng = 0; ng < 4; ng++) {
                ldsm_x4(t4, sKh_u + ((ng*16 + lr)*SR + kc*16 + lc*8)*2);
                bfr[2*ng][0]   = t4[0]; bfr[2*ng][1]   = t4[2];
                bfr[2*ng+1][0] = t4[1]; bfr[2*ng+1][1] = t4[3];
            }
#pragma unroll
            for (int nt = 0; nt < 8; nt++) mma16816(sc[nt], Qh[kc], bfr[nt]);
        }
#pragma unroll
        for (int kc = 0; kc < 4; kc++) {
#pragma unroll
            for (int ng = 0; ng < 4; ng++) {
                ldsm_x4(t4, sKl_u + ((ng*16 + lr)*SR + kc*16 + lc*8)*2);
                bfr[2*ng][0]   = t4[0]; bfr[2*ng][1]   = t4[2];
                bfr[2*ng+1][0] = t4[1]; bfr[2*ng+1][1] = t4[3];
            }
#pragma unroll
            for (int nt = 0; nt < 8; nt++) mma16816(sc[nt], Qh[kc], bfr[nt]);
        }
#pragma unroll
        for (int kc = 0; kc < 4; kc++) {
#pragma unroll
            for (int ng = 0; ng < 4; ng++) {
                ldsm_x4(t4, sKh_u + ((ng*16 + lr)*SR + kc*16 + lc*8)*2);
                bfr[2*ng][0]   = t4[0]; bfr[2*ng][1]   = t4[2];
                bfr[2*ng+1][0] = t4[1]; bfr[2*ng+1][1] = t4[3];
            }
#pragma unroll
            for (int nt = 0; nt < 8; nt++) mma16816(sc[nt], Ql[kc], bfr[nt]);
        }

#pragma unroll
        for (int nt = 0; nt < 8; nt++) {
            int key0 = kt*64 + nt*8 + cp;
            int p0 = spm[nt*8 + cp], p1 = spm[nt*8 + cp + 1];
#pragma unroll
            for (int h = 0; h < 2; h++) {
                int q = qt*64 + w*16 + grp + h*8;
                float s0 = sc[nt][2*h]   * 0.125f;
                float s1 = sc[nt][2*h+1] * 0.125f;
                if (key0 > q     || p0 == 0) s0 = -1e30f;
                if (key0 + 1 > q || p1 == 0) s1 = -1e30f;
                sc[nt][2*h]   = s0;
                sc[nt][2*h+1] = s1;
            }
        }

#pragma unroll
        for (int h = 0; h < 2; h++) {
            float vmax = -1e30f;
#pragma unroll
            for (int nt = 0; nt < 8; nt++)
                vmax = fmaxf(vmax, fmaxf(sc[nt][2*h], sc[nt][2*h+1]));
            vmax = fmaxf(vmax, __shfl_xor_sync(0xffffffffu, vmax, 1));
            vmax = fmaxf(vmax, __shfl_xor_sync(0xffffffffu, vmax, 2));
            float mn = fmaxf(mrow[h], vmax);
            float psum = 0.f;
#pragma unroll
            for (int nt = 0; nt < 8; nt++) {
                float p0 = __expf(sc[nt][2*h]   - mn);
                float p1 = __expf(sc[nt][2*h+1] - mn);
                sc[nt][2*h] = p0; sc[nt][2*h+1] = p1;
                psum += p0 + p1;
            }
            psum += __shfl_xor_sync(0xffffffffu, psum, 1);
            psum += __shfl_xor_sync(0xffffffffu, psum, 2);
            float alpha = __expf(mrow[h] - mn);
            lrow[h] = lrow[h] * alpha + psum;
            mrow[h] = mn;
#pragma unroll
            for (int nt = 0; nt < 8; nt++) {
                o[nt][2*h]   *= alpha;
                o[nt][2*h+1] *= alpha;
            }
        }

        uint32_t Ph[4][4], Pl[4][4];
#pragma unroll
        for (int kc = 0; kc < 4; kc++) {
            const int t0 = 2*kc, t1 = 2*kc + 1;
            float hv[8], lv[8];
#pragma unroll
            for (int e = 0; e < 4; e++) {
                float p0 = sc[t0][e], p1 = sc[t1][e];
                float h0 = __bfloat162float(__float2bfloat16(p0));
                float h1 = __bfloat162float(__float2bfloat16(p1));
                hv[e] = h0; hv[4+e] = h1;
                lv[e] = p0 - h0; lv[4+e] = p1 - h1;
            }
            Ph[kc][0] = packbf(hv[0], hv[1]); Ph[kc][1] = packbf(hv[2], hv[3]);
            Ph[kc][2] = packbf(hv[4], hv[5]); Ph[kc][3] = packbf(hv[6], hv[7]);
            Pl[kc][0] = packbf(lv[0], lv[1]); Pl[kc][1] = packbf(lv[2], lv[3]);
            Pl[kc][2] = packbf(lv[4], lv[5]); Pl[kc][3] = packbf(lv[6], lv[7]);
        }

#pragma unroll
        for (int kc = 0; kc < 4; kc++) {
#pragma unroll
            for (int ngp = 0; ngp < 4; ngp++) {
                uint32_t addr = sVh_u + ((kc*16 + vrow)*SR + ngp*16 + vcol)*2;
                ldsm_x4_t(t4, addr);
                uint32_t b0[2] = {t4[0], t4[1]}, b1[2] = {t4[2], t4[3]};
                mma16816(o[2*ngp],   Ph[kc], b0);
                mma16816(o[2*ngp+1], Ph[kc], b1);
            }
        }
#pragma unroll
        for (int kc = 0; kc < 4; kc++) {
#pragma unroll
            for (int ngp = 0; ngp < 4; ngp++) {
                uint32_t addr = sVl_u + ((kc*16 + vrow)*SR + ngp*16 + vcol)*2;
                ldsm_x4_t(t4, addr);
                uint32_t b0[2] = {t4[0], t4[1]}, b1[2] = {t4[2], t4[3]};
                mma16816(o[2*ngp],   Ph[kc], b0);
                mma16816(o[2*ngp+1], Ph[kc], b1);
            }
        }
#pragma unroll
        for (int kc = 0; kc < 4; kc++) {
#pragma unroll
            for (int ngp = 0; ngp < 4; ngp++) {
                uint32_t addr = sVh_u + ((kc*16 + vrow)*SR + ngp*16 + vcol)*2;
                ldsm_x4_t(t4, addr);
                uint32_t b0[2] = {t4[0], t4[1]}, b1[2] = {t4[2], t4[3]};
                mma16816(o[2*ngp],   Pl[kc], b0);
                mma16816(o[2*ngp+1], Pl[kc], b1);
            }
        }
    }

    // ---- finalize: write bf16 hi/lo att output directly (fused conv) ----
    const int h_ = bh & 15;
#pragma unroll
    for (int hf = 0; hf < 2; hf++) {
        float inv = 1.f / lrow[hf];
        int srow = qt*64 + w*16 + grp + hf*8;
        size_t rowbase = ((size_t)(b*S_LEN + srow)*HEADS + h_)*HD;
#pragma unroll
        for (int nt = 0; nt < 8; nt++) {
            int d = nt*8 + cp;
            float v0 = o[nt][2*hf] * inv;
            float v1 = o[nt][2*hf+1] * inv;
            __nv_bfloat16 h0 = __float2bfloat16(v0);
            __nv_bfloat16 h1 = __float2bfloat16(v1);
            __nv_bfloat16 l0 = __float2bfloat16(v0 - __bfloat162float(h0));
            __nv_bfloat16 l1 = __float2bfloat16(v1 - __bfloat162float(h1));
            *(__nv_bfloat162*)(g_atthi + rowbase + d) = __nv_bfloat162(h0, h1);
            *(__nv_bfloat162*)(g_attlo + rowbase + d) = __nv_bfloat162(l0, l1);
        }
    }
}

extern "C" void kernel_launch(void* const* d_in, const int* in_sizes, int n_in,
                              void* d_out, int out_size) {
    const float* x     = (const float*)d_in[0];
    const int*   pmask = (const int*)  d_in[1];
    const float* w_qkv = (const float*)d_in[2];
    const float* w_o   = (const float*)d_in[3];
    float* out = (float*)d_out;

    cudaFuncSetAttribute(attn_mma, cudaFuncAttributeMaxDynamicSharedMemorySize, ATTN_SMEM);
    cudaFuncSetAttribute(mma_gemm<0>, cudaFuncAttributeMaxDynamicSharedMemorySize, GEMM_SMEM);
    cudaFuncSetAttribute(mma_gemm<1>, cudaFuncAttributeMaxDynamicSharedMemorySize, GEMM_SMEM);

    rope_init_kernel<<<64, 1024>>>();
    conv_kernel<0><<<(BATCH*S_LEN*DMODEL/4 + 255)/256, 256>>>(x);
    conv_kernel<1><<<(3*DMODEL*DMODEL/4 + 255)/256, 256>>>(w_qkv);
    conv_kernel<2><<<(DMODEL*DMODEL/4 + 255)/256, 256>>>(w_o);
    mma_gemm<0><<<dim3(24, 64), 256, GEMM_SMEM>>>(nullptr);
    attn_mma<<<dim3(32, 64), 128, ATTN_SMEM>>>(pmask);
    mma_gemm<1><<<dim3(8, 64), 256, GEMM_SMEM>>>(out);
}